// round 1
// baseline (speedup 1.0000x reference)
#include <cuda_runtime.h>
#include <math.h>

#define BB 128
#define JJ 10
#define DD 16
#define II 6400
#define KK 8
#define CC 32
#define REP 200

// Scratch (static device globals: allocation-free per harness rules)
__device__ float g_uhat[(size_t)BB * JJ * II * DD];   // 524 MB  [b,j,i,d]
__device__ float g_coef[(size_t)BB * JJ * II];        //  33 MB  [b,j,i]
__device__ float g_V[BB * JJ * DD];                   // running sum of outputs (logit vector)

// ---------------------------------------------------------------------------
// K1: u_hat[b,j,i,d] = sum_k x[b,i,k] * W[j, i/200, d, k]
// grid (I/256, J, B), block 256, thread-per-i
// ---------------------------------------------------------------------------
__global__ void k_uhat(const float* __restrict__ x, const float* __restrict__ W) {
    const int i0  = blockIdx.x * 256;
    const int j   = blockIdx.y;
    const int b   = blockIdx.z;
    const int tid = threadIdx.x;

    __shared__ float Ws[3 * DD * KK];          // up to 3 channels span a 256-wide i tile
    const int c0 = i0 / REP;
    const int c1 = (i0 + 255) / REP;
    const int nW = (c1 - c0 + 1) * DD * KK;
    for (int t = tid; t < nW; t += 256)
        Ws[t] = W[(size_t)(j * CC + c0) * DD * KK + t];
    __syncthreads();

    const int i = i0 + tid;
    const float4* xp = reinterpret_cast<const float4*>(x + ((size_t)b * II + i) * KK);
    const float4 xa = xp[0], xb = xp[1];
    const float xv[8] = {xa.x, xa.y, xa.z, xa.w, xb.x, xb.y, xb.z, xb.w};
    const float* Wc = Ws + (i / REP - c0) * DD * KK;

    float4 o[4];
    float* of = reinterpret_cast<float*>(o);
#pragma unroll
    for (int d = 0; d < DD; d++) {
        float acc = 0.f;
#pragma unroll
        for (int k = 0; k < KK; k++) acc = fmaf(xv[k], Wc[d * KK + k], acc);
        of[d] = acc;
    }
    float4* up = reinterpret_cast<float4*>(g_uhat + (((size_t)b * JJ + j) * II + i) * DD);
    up[0] = o[0]; up[1] = o[1]; up[2] = o[2]; up[3] = o[3];
}

// ---------------------------------------------------------------------------
// K0: iteration 0 via channel-sum trick.
// out0[b,j,:] = squash(0.1 * sum_{c,k} S[b,c,k] W[j,c,:,k] + B),  S = per-channel input sum
// grid (B), block 256
// ---------------------------------------------------------------------------
__global__ void k_iter0(const float* __restrict__ x, const float* __restrict__ W,
                        const float* __restrict__ Bv) {
    const int b   = blockIdx.x;
    const int tid = threadIdx.x;
    __shared__ float S[CC * KK];     // 256
    __shared__ float vbuf[JJ * DD];  // 160

    {   // S[c,k] = sum over 200 capsules in channel c
        const int c = tid >> 3, k = tid & 7;
        const float* xp = x + (size_t)b * II * KK + (size_t)c * REP * KK + k;
        float s = 0.f;
        for (int ii = 0; ii < REP; ii++) s += xp[ii * KK];
        S[tid] = s;
    }
    __syncthreads();

    if (tid < JJ * DD) {
        const int j = tid / DD, d = tid % DD;
        float acc = 0.f;
#pragma unroll 4
        for (int c = 0; c < CC; c++)
#pragma unroll
            for (int k = 0; k < KK; k++)
                acc = fmaf(S[c * KK + k], W[(((size_t)j * CC + c) * DD + d) * KK + k], acc);
        vbuf[tid] = 0.1f * acc + Bv[tid];
    }
    __syncthreads();

    if (tid < JJ * DD) {
        const int j = tid / DD;
        float s = 0.f;
#pragma unroll
        for (int d2 = 0; d2 < DD; d2++) { const float v = vbuf[j * DD + d2]; s += v * v; }
        const float f = sqrtf(s) / (1.0f + s);
        g_V[(size_t)b * JJ * DD + tid] = vbuf[tid] * f;
    }
}

// ---------------------------------------------------------------------------
// Kc: coupling coefficients. logit[j] = V[b,j,:] . u_hat[b,j,i,:]; softmax over j.
// grid (I/256, B), block 256, thread-per-i
// ---------------------------------------------------------------------------
__global__ void k_softmax() {
    const int b = blockIdx.y;
    const int i = blockIdx.x * 256 + threadIdx.x;

    __shared__ float Vs[JJ * DD];
    if (threadIdx.x < JJ * DD) Vs[threadIdx.x] = g_V[(size_t)b * JJ * DD + threadIdx.x];
    __syncthreads();

    float logit[JJ];
#pragma unroll
    for (int j = 0; j < JJ; j++) {
        const float4* up = reinterpret_cast<const float4*>(
            g_uhat + (((size_t)b * JJ + j) * II + i) * DD);
        float l = 0.f;
#pragma unroll
        for (int q = 0; q < 4; q++) {
            const float4 u = up[q];
            l = fmaf(u.x, Vs[j * DD + q * 4 + 0], l);
            l = fmaf(u.y, Vs[j * DD + q * 4 + 1], l);
            l = fmaf(u.z, Vs[j * DD + q * 4 + 2], l);
            l = fmaf(u.w, Vs[j * DD + q * 4 + 3], l);
        }
        logit[j] = l;
    }
    float m = logit[0];
#pragma unroll
    for (int j = 1; j < JJ; j++) m = fmaxf(m, logit[j]);
    float e[JJ], sum = 0.f;
#pragma unroll
    for (int j = 0; j < JJ; j++) { e[j] = __expf(logit[j] - m); sum += e[j]; }
    const float r = 1.0f / sum;
#pragma unroll
    for (int j = 0; j < JJ; j++)
        g_coef[((size_t)b * JJ + j) * II + i] = e[j] * r;
}

// ---------------------------------------------------------------------------
// Ks: s[b,j,:] = sum_i c[b,j,i] * u_hat[b,j,i,:]; out = squash(s + B).
// addV=1 -> g_V += out (intermediate iter); addV=0 -> write final to out.
// grid (J, B), block 256
// ---------------------------------------------------------------------------
__global__ void k_accum(const float* __restrict__ Bv, float* __restrict__ out, int addV) {
    const int j   = blockIdx.x;
    const int b   = blockIdx.y;
    const int tid = threadIdx.x;

    float acc[DD];
#pragma unroll
    for (int d = 0; d < DD; d++) acc[d] = 0.f;

    const float* cp = g_coef + ((size_t)b * JJ + j) * II;
    const float* up = g_uhat + (((size_t)b * JJ + j) * II) * (size_t)DD;

    for (int i = tid; i < II; i += 256) {
        const float cc = cp[i];
        const float4* u4 = reinterpret_cast<const float4*>(up + (size_t)i * DD);
#pragma unroll
        for (int q = 0; q < 4; q++) {
            const float4 u = u4[q];
            acc[q * 4 + 0] = fmaf(cc, u.x, acc[q * 4 + 0]);
            acc[q * 4 + 1] = fmaf(cc, u.y, acc[q * 4 + 1]);
            acc[q * 4 + 2] = fmaf(cc, u.z, acc[q * 4 + 2]);
            acc[q * 4 + 3] = fmaf(cc, u.w, acc[q * 4 + 3]);
        }
    }

    // cross-warp reduction
    __shared__ float red[8][DD];
    __shared__ float vfin[DD + 1];
    const int lane = tid & 31, wid = tid >> 5;
#pragma unroll
    for (int d = 0; d < DD; d++)
#pragma unroll
        for (int o = 16; o > 0; o >>= 1)
            acc[d] += __shfl_down_sync(0xffffffffu, acc[d], o);
    if (lane == 0)
#pragma unroll
        for (int d = 0; d < DD; d++) red[wid][d] = acc[d];
    __syncthreads();

    if (tid < DD) {
        float v = Bv[j * DD + tid];
#pragma unroll
        for (int w = 0; w < 8; w++) v += red[w][tid];
        vfin[tid] = v;
    }
    __syncthreads();
    if (tid == 0) {
        float s = 0.f;
#pragma unroll
        for (int d = 0; d < DD; d++) s += vfin[d] * vfin[d];
        vfin[DD] = sqrtf(s) / (1.0f + s);
    }
    __syncthreads();
    if (tid < DD) {
        const float o = vfin[tid] * vfin[DD];
        if (addV) g_V[((size_t)b * JJ + j) * DD + tid] += o;
        else      out[((size_t)b * JJ + j) * DD + tid]  = o;
    }
}

// ---------------------------------------------------------------------------
extern "C" void kernel_launch(void* const* d_in, const int* in_sizes, int n_in,
                              void* d_out, int out_size) {
    const float* x  = (const float*)d_in[0];  // [128, 6400, 8]
    const float* W  = (const float*)d_in[1];  // [10, 32, 16, 8]
    const float* Bv = (const float*)d_in[2];  // [10, 16]
    float* out = (float*)d_out;               // [128, 10, 16]

    k_uhat<<<dim3(II / 256, JJ, BB), 256>>>(x, W);
    k_iter0<<<BB, 256>>>(x, W, Bv);

    // routing iteration 1
    k_softmax<<<dim3(II / 256, BB), 256>>>();
    k_accum<<<dim3(JJ, BB), 256>>>(Bv, nullptr, 1);

    // routing iteration 2 (final)
    k_softmax<<<dim3(II / 256, BB), 256>>>();
    k_accum<<<dim3(JJ, BB), 256>>>(Bv, out, 0);
}

// round 2
// speedup vs baseline: 4.3794x; 4.3794x over previous
#include <cuda_runtime.h>
#include <math.h>

#define BB 128
#define JJ 10
#define DD 16
#define II 6400
#define KK 8
#define CC 32
#define REP 200   // capsules per channel

// Tiny scratch only (no u_hat!)
__device__ float g_T[(size_t)BB * CC * JJ * KK];   // 1.3 MB  [b,c,j,k]
__device__ float g_V[BB * JJ * DD];                // running sum of outputs

// ---------------------------------------------------------------------------
// k_route: one block per (channel c, batch b). 256 threads.
//   iter==0: coef = 1/J uniform.
//   iter>0 : P[j,k] = sum_d V[b,j,d] * W[j,c,d,k];
//            logit[j,i] = sum_k x[i,k] * P[j,k]; softmax over j -> coef.
//   T[b,c,j,k] = sum_{i in channel} coef[j,i] * x[i,k]
// ---------------------------------------------------------------------------
__global__ __launch_bounds__(256) void k_route(const float* __restrict__ x,
                                               const float* __restrict__ W,
                                               int iter) {
    const int c   = blockIdx.x;
    const int b   = blockIdx.y;
    const int tid = threadIdx.x;

    __shared__ float xs[REP * KK];      // 1600 floats: x tile for this channel
    __shared__ float Ps[JJ * KK];       // 80
    __shared__ float Vs[JJ * DD];       // 160
    __shared__ float cs[REP * JJ];      // 2000 floats: staged coupling coeffs

    // load x tile: 1600 floats = 400 float4, fully coalesced
    {
        const float4* xp = reinterpret_cast<const float4*>(
            x + (size_t)b * II * KK + (size_t)c * REP * KK);
        float4* xd = reinterpret_cast<float4*>(xs);
        for (int t = tid; t < REP * KK / 4; t += 256) xd[t] = xp[t];
    }

    if (iter > 0) {
        if (tid < JJ * DD) Vs[tid] = g_V[b * JJ * DD + tid];
        __syncthreads();
        if (tid < JJ * KK) {
            const int j = tid >> 3, k = tid & 7;
            const float* Wp = W + ((size_t)(j * CC + c) * DD) * KK + k;  // stride KK over d
            float acc = 0.f;
#pragma unroll
            for (int d = 0; d < DD; d++) acc = fmaf(Vs[j * DD + d], Wp[d * KK], acc);
            Ps[tid] = acc;
        }
    }
    __syncthreads();

    // per-capsule softmax -> staged coefs
    if (tid < REP) {
        float xv[KK];
        const float4* x4 = reinterpret_cast<const float4*>(xs + tid * KK);
        float4 a = x4[0], bq = x4[1];
        xv[0]=a.x; xv[1]=a.y; xv[2]=a.z; xv[3]=a.w;
        xv[4]=bq.x; xv[5]=bq.y; xv[6]=bq.z; xv[7]=bq.w;

        if (iter == 0) {
#pragma unroll
            for (int j = 0; j < JJ; j++) cs[tid * JJ + j] = 0.1f;
        } else {
            float logit[JJ];
#pragma unroll
            for (int j = 0; j < JJ; j++) {
                float l = 0.f;
#pragma unroll
                for (int k = 0; k < KK; k++) l = fmaf(xv[k], Ps[j * KK + k], l);
                logit[j] = l;
            }
            float m = logit[0];
#pragma unroll
            for (int j = 1; j < JJ; j++) m = fmaxf(m, logit[j]);
            float e[JJ], sum = 0.f;
#pragma unroll
            for (int j = 0; j < JJ; j++) { e[j] = __expf(logit[j] - m); sum += e[j]; }
            const float r = 1.0f / sum;
#pragma unroll
            for (int j = 0; j < JJ; j++) cs[tid * JJ + j] = e[j] * r;
        }
    }
    __syncthreads();

    // reducers: T[j,k] = sum_{t<200} cs[t,j] * xs[t,k]
    if (tid < JJ * KK) {
        const int j = tid >> 3, k = tid & 7;
        float a0 = 0.f, a1 = 0.f, a2 = 0.f, a3 = 0.f;
#pragma unroll 4
        for (int t = 0; t < REP; t += 4) {
            a0 = fmaf(cs[(t + 0) * JJ + j], xs[(t + 0) * KK + k], a0);
            a1 = fmaf(cs[(t + 1) * JJ + j], xs[(t + 1) * KK + k], a1);
            a2 = fmaf(cs[(t + 2) * JJ + j], xs[(t + 2) * KK + k], a2);
            a3 = fmaf(cs[(t + 3) * JJ + j], xs[(t + 3) * KK + k], a3);
        }
        g_T[((size_t)b * CC + c) * JJ * KK + tid] = (a0 + a1) + (a2 + a3);
    }
}

// ---------------------------------------------------------------------------
// k_update: one block per batch b. 256 threads (160 active).
//   s[j,d] = sum_{c,k} W[j,c,d,k] * T[b,c,j,k] + B[j,d];  out = squash(s)
//   mode 0: g_V  = out      (after iter 0)
//   mode 1: g_V += out      (after iter 1)
//   mode 2: d_out = out     (final)
// ---------------------------------------------------------------------------
__global__ __launch_bounds__(256) void k_update(const float* __restrict__ W,
                                                const float* __restrict__ Bv,
                                                float* __restrict__ out, int mode) {
    const int b   = blockIdx.x;
    const int tid = threadIdx.x;

    __shared__ float vbuf[JJ * DD];
    __shared__ float fbuf[JJ];

    if (tid < JJ * DD) {
        const int j = tid / DD, d = tid % DD;
        // W element (j,c,d,k) at j*4096 + c*128 + d*8 + k
        const float4* Wp = reinterpret_cast<const float4*>(W + (size_t)j * CC * DD * KK + d * KK);
        // T element (b,c,j,k) at b*2560 + c*80 + j*8 + k
        const float4* Tp = reinterpret_cast<const float4*>(g_T + (size_t)b * CC * JJ * KK + j * KK);
        float acc = 0.f;
#pragma unroll 8
        for (int cc = 0; cc < CC; cc++) {
            const float4 w0 = Wp[cc * 32];       // 128 floats / 4
            const float4 w1 = Wp[cc * 32 + 1];
            const float4 t0 = Tp[cc * 20];       // 80 floats / 4
            const float4 t1 = Tp[cc * 20 + 1];
            acc = fmaf(w0.x, t0.x, acc); acc = fmaf(w0.y, t0.y, acc);
            acc = fmaf(w0.z, t0.z, acc); acc = fmaf(w0.w, t0.w, acc);
            acc = fmaf(w1.x, t1.x, acc); acc = fmaf(w1.y, t1.y, acc);
            acc = fmaf(w1.z, t1.z, acc); acc = fmaf(w1.w, t1.w, acc);
        }
        vbuf[tid] = acc + Bv[tid];
    }
    __syncthreads();
    if (tid < JJ) {
        float s = 0.f;
#pragma unroll
        for (int d = 0; d < DD; d++) { const float v = vbuf[tid * DD + d]; s += v * v; }
        fbuf[tid] = sqrtf(s) / (1.0f + s);
    }
    __syncthreads();
    if (tid < JJ * DD) {
        const float o = vbuf[tid] * fbuf[tid / DD];
        if (mode == 0)      g_V[b * JJ * DD + tid]  = o;
        else if (mode == 1) g_V[b * JJ * DD + tid] += o;
        else                out[(size_t)b * JJ * DD + tid] = o;
    }
}

// ---------------------------------------------------------------------------
extern "C" void kernel_launch(void* const* d_in, const int* in_sizes, int n_in,
                              void* d_out, int out_size) {
    const float* x  = (const float*)d_in[0];  // [128, 6400, 8]
    const float* W  = (const float*)d_in[1];  // [10, 32, 16, 8]
    const float* Bv = (const float*)d_in[2];  // [10, 16]
    float* out = (float*)d_out;               // [128, 10, 16]

    const dim3 gr(CC, BB);

    // iteration 0: uniform coupling
    k_route<<<gr, 256>>>(x, W, 0);
    k_update<<<BB, 256>>>(W, Bv, nullptr, 0);

    // iteration 1
    k_route<<<gr, 256>>>(x, W, 1);
    k_update<<<BB, 256>>>(W, Bv, nullptr, 1);

    // iteration 2 (final)
    k_route<<<gr, 256>>>(x, W, 2);
    k_update<<<BB, 256>>>(W, Bv, out, 2);
}

// round 3
// speedup vs baseline: 6.0449x; 1.3803x over previous
#include <cuda_runtime.h>
#include <math.h>

#define BB 128
#define JJ 10
#define DD 16
#define II 6400
#define KK 8
#define CC 32
#define REP 200          // capsules per channel
#define NSTEP 16         // 2 channels per step
#define NVS   (3 * NSTEP)

// smem layout (floats)
#define OFF_XS   0                    // 2 bufs * 2 ch * 200*8 = 6400
#define OFF_PQ   6400                 // 32*10*8 = 2560
#define OFF_CS   8960                 // 2 ch * 200*11 = 4400
#define OFF_PART 13360                // 2*12*20*4 = 1920
#define OFF_TT   15280                // 160
#define OFF_SV   15440                // 160
#define OFF_VV   15600                // 160
#define OFF_FB   15760                // 16
#define SMEM_FLOATS 15776
#define SMEM_BYTES (SMEM_FLOATS * 4)

__device__ __forceinline__ void cp16(float* dst, const float* src) {
    unsigned sdst = (unsigned)__cvta_generic_to_shared(dst);
    asm volatile("cp.async.cg.shared.global [%0], [%1], 16;\n" :: "r"(sdst), "l"(src));
}
__device__ __forceinline__ void cp_commit() { asm volatile("cp.async.commit_group;\n"); }
__device__ __forceinline__ void cp_wait0()  { asm volatile("cp.async.wait_group 0;\n"); }

__global__ __launch_bounds__(512, 1) void caps_fused(const float* __restrict__ x,
                                                     const float* __restrict__ W,
                                                     const float* __restrict__ Bv,
                                                     float* __restrict__ out) {
    extern __shared__ float sm[];
    float* xs   = sm + OFF_XS;    // [2][3200]
    float* Pq   = sm + OFF_PQ;    // [c][j][k]
    float* cs   = sm + OFF_CS;    // [ch][i*11 + j]
    float* part = sm + OFF_PART;  // [ch][chunk][g][4]
    float* Tt   = sm + OFF_TT;    // [ch][j*8+k]
    float* sv   = sm + OFF_SV;
    float* Vv   = sm + OFF_VV;
    float* fb   = sm + OFF_FB;

    const int b   = blockIdx.x;
    const int tid = threadIdx.x;
    const float* xb = x + (size_t)b * II * KK;

    // prefetch virtual-step 0 tile (channels 0,1 : 3200 contiguous floats)
    {
        const float* src = xb;
        if (tid < 800) cp16(xs + tid * 4, src + tid * 4);
        if (tid < 288) cp16(xs + (tid + 512) * 4, src + (tid + 512) * 4);
        cp_commit();
    }

    float sreg = 0.f;  // s[j,d] accumulator for tid<160

    for (int it = 0; it < 3; ++it) {
        if (it == 0) {
            // uniform coupling: fill cs with 0.1 once
            for (int t = tid; t < 2 * REP * 11; t += 512) cs[t] = 0.1f;
        } else {
            // P[c,j,k] = sum_d Vv[j,d] * W[j,c,d,k]   (warp per (j,c) pair)
            const int w = tid >> 5, l = tid & 31;
            const int d = l >> 1, kh = l & 1;
#pragma unroll 4
            for (int n = 0; n < 20; ++n) {
                const int p = w + (n << 4);      // 0..319
                const int j = p / CC, c = p % CC;
                const float4 wv = *reinterpret_cast<const float4*>(
                    W + ((size_t)(j * CC + c)) * 128 + l * 4);
                const float v = Vv[j * DD + d];
                float p0 = v * wv.x, p1 = v * wv.y, p2 = v * wv.z, p3 = v * wv.w;
#pragma unroll
                for (int m = 2; m <= 16; m <<= 1) {
                    p0 += __shfl_xor_sync(0xffffffffu, p0, m);
                    p1 += __shfl_xor_sync(0xffffffffu, p1, m);
                    p2 += __shfl_xor_sync(0xffffffffu, p2, m);
                    p3 += __shfl_xor_sync(0xffffffffu, p3, m);
                }
                if (l < 2) {
                    float4 r = make_float4(p0, p1, p2, p3);
                    *reinterpret_cast<float4*>(Pq + (c * JJ + j) * KK + kh * 4) = r;
                }
            }
        }
        if (tid < 160) sreg = 0.f;

        for (int s = 0; s < NSTEP; ++s) {
            const int vs = it * NSTEP + s;
            cp_wait0();
            __syncthreads();              // tile vs ready, prev step fully done

            // prefetch next virtual step
            if (vs + 1 < NVS) {
                const int nt = (vs + 1) % NSTEP;       // tile index
                const float* src = xb + nt * 3200;
                float* dst = xs + ((vs + 1) & 1) * 3200;
                if (tid < 800) cp16(dst + tid * 4, src + tid * 4);
                if (tid < 288) cp16(dst + (tid + 512) * 4, src + (tid + 512) * 4);
                cp_commit();
            }
            const float* xt = xs + (vs & 1) * 3200;

            // ---- phase A: logits + softmax -> cs (iter>0 only) ----
            if (it > 0 && tid < 2 * REP) {
                const int ch = (tid >= REP);
                const int i  = tid - ch * REP;
                const int c  = s * 2 + ch;
                const float4 xa = *reinterpret_cast<const float4*>(xt + ch * 1600 + i * 8);
                const float4 xc = *reinterpret_cast<const float4*>(xt + ch * 1600 + i * 8 + 4);
                float logit[JJ];
#pragma unroll
                for (int j = 0; j < JJ; ++j) {
                    const float4 p0 = *reinterpret_cast<const float4*>(Pq + (c * JJ + j) * KK);
                    const float4 p1 = *reinterpret_cast<const float4*>(Pq + (c * JJ + j) * KK + 4);
                    float l = 0.f;
                    l = fmaf(xa.x, p0.x, l); l = fmaf(xa.y, p0.y, l);
                    l = fmaf(xa.z, p0.z, l); l = fmaf(xa.w, p0.w, l);
                    l = fmaf(xc.x, p1.x, l); l = fmaf(xc.y, p1.y, l);
                    l = fmaf(xc.z, p1.z, l); l = fmaf(xc.w, p1.w, l);
                    logit[j] = l;
                }
                float m = logit[0];
#pragma unroll
                for (int j = 1; j < JJ; ++j) m = fmaxf(m, logit[j]);
                float e[JJ], sum = 0.f;
#pragma unroll
                for (int j = 0; j < JJ; ++j) { e[j] = __expf(logit[j] - m); sum += e[j]; }
                const float r = __fdividef(1.0f, sum);
                float* cw = cs + ch * (REP * 11) + i * 11;
#pragma unroll
                for (int j = 0; j < JJ; ++j) cw[j] = e[j] * r;
            }
            __syncthreads();

            // ---- phase B: partial T ----
            {
                const int local = tid & 255;
                if (local < 240) {
                    const int ch = tid >> 8;
                    const int g = local % 20;        // g = j*2 + kh
                    const int chunk = local / 20;    // 0..11
                    const int kh = g & 1, j = g >> 1;
                    const int i0 = chunk * 17;
                    const int i1 = (i0 + 17 < REP) ? i0 + 17 : REP;
                    float a0 = 0.f, a1 = 0.f, a2 = 0.f, a3 = 0.f;
                    const float* xp = xt + ch * 1600 + i0 * 8 + kh * 4;
                    const float* cp = cs + ch * (REP * 11) + i0 * 11 + j;
#pragma unroll 4
                    for (int i = i0; i < i1; ++i) {
                        const float4 xv = *reinterpret_cast<const float4*>(xp);
                        const float cf = *cp;
                        a0 = fmaf(cf, xv.x, a0); a1 = fmaf(cf, xv.y, a1);
                        a2 = fmaf(cf, xv.z, a2); a3 = fmaf(cf, xv.w, a3);
                        xp += 8; cp += 11;
                    }
                    *reinterpret_cast<float4*>(part + ((ch * 12 + chunk) * 20 + g) * 4) =
                        make_float4(a0, a1, a2, a3);
                }
            }
            __syncthreads();

            // ---- phase C: combine partials -> Tt ----
            if (tid < 160) {
                const int ch = tid / 80, e = tid % 80;
                const int j = e >> 3, k = e & 7;
                const int g = j * 2 + (k >> 2), q = k & 3;
                float t = 0.f;
#pragma unroll
                for (int chunk = 0; chunk < 12; ++chunk)
                    t += part[((ch * 12 + chunk) * 20 + g) * 4 + q];
                Tt[tid] = t;
            }
            __syncthreads();

            // ---- phase D: s[j,d] += sum_k W[j,c,d,k] * Tt[ch][j,k] ----
            if (tid < 160) {
                const int j = tid / DD, d = tid % DD;
#pragma unroll
                for (int ch = 0; ch < 2; ++ch) {
                    const int c = s * 2 + ch;
                    const float4 w0 = *reinterpret_cast<const float4*>(
                        W + ((size_t)(j * CC + c)) * 128 + d * 8);
                    const float4 w1 = *reinterpret_cast<const float4*>(
                        W + ((size_t)(j * CC + c)) * 128 + d * 8 + 4);
                    const float4 t0 = *reinterpret_cast<const float4*>(Tt + ch * 80 + j * 8);
                    const float4 t1 = *reinterpret_cast<const float4*>(Tt + ch * 80 + j * 8 + 4);
                    sreg = fmaf(w0.x, t0.x, sreg); sreg = fmaf(w0.y, t0.y, sreg);
                    sreg = fmaf(w0.z, t0.z, sreg); sreg = fmaf(w0.w, t0.w, sreg);
                    sreg = fmaf(w1.x, t1.x, sreg); sreg = fmaf(w1.y, t1.y, sreg);
                    sreg = fmaf(w1.z, t1.z, sreg); sreg = fmaf(w1.w, t1.w, sreg);
                }
            }
            // next step's barriers protect Tt/part reuse
        }

        // ---- iter finalize: squash, update V / write out ----
        __syncthreads();
        if (tid < 160) sv[tid] = sreg + Bv[tid];
        __syncthreads();
        if (tid < JJ) {
            float sq = 0.f;
#pragma unroll
            for (int d = 0; d < DD; ++d) { const float v = sv[tid * DD + d]; sq += v * v; }
            fb[tid] = sqrtf(sq) / (1.0f + sq);
        }
        __syncthreads();
        if (tid < 160) {
            const float o = sv[tid] * fb[tid / DD];
            if (it == 0)      Vv[tid] = o;
            else if (it == 1) Vv[tid] += o;
            else              out[(size_t)b * 160 + tid] = o;
        }
        __syncthreads();   // Vv ready for next iter's P compute
    }
}

extern "C" void kernel_launch(void* const* d_in, const int* in_sizes, int n_in,
                              void* d_out, int out_size) {
    const float* x  = (const float*)d_in[0];  // [128, 6400, 8]
    const float* W  = (const float*)d_in[1];  // [10, 32, 16, 8]
    const float* Bv = (const float*)d_in[2];  // [10, 16]
    float* out = (float*)d_out;               // [128, 10, 16]

    cudaFuncSetAttribute(caps_fused, cudaFuncAttributeMaxDynamicSharedMemorySize, SMEM_BYTES);
    caps_fused<<<BB, 512, SMEM_BYTES>>>(x, W, Bv, out);
}

// round 4
// speedup vs baseline: 7.7677x; 1.2850x over previous
#include <cuda_runtime.h>
#include <math.h>

#define BB 128
#define JJ 10
#define DD 16
#define II 6400
#define KK 8
#define CC 32
#define REP 200        // capsules per channel
#define GC  16         // channel-groups per batch (2 channels each)

__device__ float g_V[BB * 160];             // running sum of outputs (logit vector)
__device__ float g_part[BB * GC * 160];     // per-group partial s
__device__ int   g_cnt[BB];                 // finisher election (zero-init, reset each launch)

__device__ __forceinline__ void cp16(float* dst, const float* src) {
    unsigned sdst = (unsigned)__cvta_generic_to_shared(dst);
    asm volatile("cp.async.cg.shared.global [%0], [%1], 16;\n" :: "r"(sdst), "l"(src));
}
__device__ __forceinline__ void cp_commit() { asm volatile("cp.async.commit_group;\n"); }
__device__ __forceinline__ void cp_wait0()  { asm volatile("cp.async.wait_group 0;\n"); }

// ---------------------------------------------------------------------------
// One routing iteration. grid (GC, BB), block 256.
// Block handles channels c0=2*gc, c0+1 (400 capsules):
//   it==0: uniform coupling shortcut  T[ch,k] = 0.1 * sum_i x[i,k]
//   it>0 : P[ch,j,k] = sum_d V[j,d] W[j,c,d,k]; logits -> softmax -> coefs
//          T[ch,j,k] = sum_i coef[i,j] x[i,k]
//   partial s[j,d] = sum_{ch,k} W[j,c,d,k] T -> g_part
//   last block per batch: sum partials, +B, squash, update V / write out.
// ---------------------------------------------------------------------------
__global__ __launch_bounds__(256) void k_iter(const float* __restrict__ x,
                                              const float* __restrict__ W,
                                              const float* __restrict__ Bv,
                                              float* __restrict__ out, int it) {
    __shared__ float xs[3200];     // [ch][i][k]
    __shared__ float Pq[160];      // [ch][j][k]
    __shared__ float cs[4400];     // [ch][i*11 + j]
    __shared__ float part[960];    // [(chunk*40+g)*4+q]
    __shared__ float Tt[160];      // [ch*80 + j*8 + k]  (it0: [ch*8+k], 16 used)
    __shared__ float Vs[160];
    __shared__ float red[176];     // finisher scratch: 160 s-values + 16 factors
    __shared__ int   lastFlag;

    const int gc  = blockIdx.x;
    const int b   = blockIdx.y;
    const int tid = threadIdx.x;
    const int c0  = gc * 2;
    const float* xb = x + ((size_t)b * II + (size_t)c0 * REP) * KK;   // 3200 floats

    // async load of the x tile
    for (int t = tid; t < 800; t += 256) cp16(xs + t * 4, xb + t * 4);
    cp_commit();

    if (it > 0) {
        if (tid < 160) Vs[tid] = g_V[b * 160 + tid];
        __syncthreads();
        if (tid < 160) {      // P[ch,j,k] = sum_d V[j,d] * W[j,c0+ch,d,k]
            const int ch = tid / 80, r = tid % 80, j = r >> 3, k = r & 7;
            const float* Wp = W + ((size_t)(j * CC + c0 + ch)) * 128 + k;
            float acc = 0.f;
#pragma unroll
            for (int d = 0; d < DD; ++d) acc = fmaf(Vs[j * DD + d], Wp[d * 8], acc);
            Pq[ch * 80 + j * 8 + k] = acc;
        }
    }
    cp_wait0();
    __syncthreads();

    float sreg = 0.f;   // partial s[j,d] for tid<160

    if (it == 0) {
        // Sx[ch,k] partials: 160 threads, (ch,k,sub), 20 caps each
        if (tid < 160) {
            const int ch = tid / 80, r = tid % 80, k = r & 7, sub = r >> 3;
            float a = 0.f;
            const float* xp = xs + ch * 1600 + sub * 160 + k;
#pragma unroll 4
            for (int i = 0; i < 20; ++i) a += xp[i * 8];
            part[tid] = a;
        }
        __syncthreads();
        if (tid < 16) {
            const int ch = tid >> 3, k = tid & 7;
            float a = 0.f;
#pragma unroll
            for (int sub = 0; sub < 10; ++sub) a += part[ch * 80 + sub * 8 + k];
            Tt[tid] = 0.1f * a;
        }
        __syncthreads();
        if (tid < 160) {
            const int j = tid / DD, d = tid % DD;
#pragma unroll
            for (int ch = 0; ch < 2; ++ch) {
                const float4 w0 = *reinterpret_cast<const float4*>(
                    W + (size_t)(j * CC + c0 + ch) * 128 + d * 8);
                const float4 w1 = *reinterpret_cast<const float4*>(
                    W + (size_t)(j * CC + c0 + ch) * 128 + d * 8 + 4);
                const float4 t0 = *reinterpret_cast<const float4*>(Tt + ch * 8);
                const float4 t1 = *reinterpret_cast<const float4*>(Tt + ch * 8 + 4);
                sreg = fmaf(w0.x, t0.x, sreg); sreg = fmaf(w0.y, t0.y, sreg);
                sreg = fmaf(w0.z, t0.z, sreg); sreg = fmaf(w0.w, t0.w, sreg);
                sreg = fmaf(w1.x, t1.x, sreg); sreg = fmaf(w1.y, t1.y, sreg);
                sreg = fmaf(w1.z, t1.z, sreg); sreg = fmaf(w1.w, t1.w, sreg);
            }
        }
        __syncthreads();
    } else {
        // ---- phase A: logits + softmax -> coefs ----
        for (int cap = tid; cap < 2 * REP; cap += 256) {
            const int ch = (cap >= REP);
            const int i  = cap - ch * REP;
            const float4 xa = *reinterpret_cast<const float4*>(xs + ch * 1600 + i * 8);
            const float4 xc = *reinterpret_cast<const float4*>(xs + ch * 1600 + i * 8 + 4);
            float logit[JJ];
#pragma unroll
            for (int j = 0; j < JJ; ++j) {
                const float4 p0 = *reinterpret_cast<const float4*>(Pq + ch * 80 + j * 8);
                const float4 p1 = *reinterpret_cast<const float4*>(Pq + ch * 80 + j * 8 + 4);
                float l = 0.f;
                l = fmaf(xa.x, p0.x, l); l = fmaf(xa.y, p0.y, l);
                l = fmaf(xa.z, p0.z, l); l = fmaf(xa.w, p0.w, l);
                l = fmaf(xc.x, p1.x, l); l = fmaf(xc.y, p1.y, l);
                l = fmaf(xc.z, p1.z, l); l = fmaf(xc.w, p1.w, l);
                logit[j] = l;
            }
            float m = logit[0];
#pragma unroll
            for (int j = 1; j < JJ; ++j) m = fmaxf(m, logit[j]);
            float e[JJ], sum = 0.f;
#pragma unroll
            for (int j = 0; j < JJ; ++j) { e[j] = __expf(logit[j] - m); sum += e[j]; }
            const float r = __fdividef(1.0f, sum);
            float* cw = cs + ch * 2200 + i * 11;
#pragma unroll
            for (int j = 0; j < JJ; ++j) cw[j] = e[j] * r;
        }
        __syncthreads();

        // ---- phase B: partial T ----
        if (tid < 240) {
            const int chunk = tid / 40, g = tid % 40;
            const int ch = g / 20, r = g % 20, j = r >> 1, kh = r & 1;
            const int i0 = chunk * 34;
            const int i1 = (i0 + 34 < REP) ? i0 + 34 : REP;
            float a0 = 0.f, a1 = 0.f, a2 = 0.f, a3 = 0.f;
            const float* xp = xs + ch * 1600 + i0 * 8 + kh * 4;
            const float* cp = cs + ch * 2200 + i0 * 11 + j;
#pragma unroll 2
            for (int i = i0; i < i1; ++i) {
                const float4 xv = *reinterpret_cast<const float4*>(xp);
                const float cf = *cp;
                a0 = fmaf(cf, xv.x, a0); a1 = fmaf(cf, xv.y, a1);
                a2 = fmaf(cf, xv.z, a2); a3 = fmaf(cf, xv.w, a3);
                xp += 8; cp += 11;
            }
            *reinterpret_cast<float4*>(part + tid * 4) = make_float4(a0, a1, a2, a3);
        }
        __syncthreads();

        // ---- phase C: combine -> Tt ----
        if (tid < 160) {
            const int ch = tid / 80, r = tid % 80, j = r >> 3, k = r & 7;
            const int g = ch * 20 + j * 2 + (k >> 2), q = k & 3;
            float t = 0.f;
#pragma unroll
            for (int chunk = 0; chunk < 6; ++chunk)
                t += part[(chunk * 40 + g) * 4 + q];
            Tt[tid] = t;
        }
        __syncthreads();

        // ---- phase D: partial s ----
        if (tid < 160) {
            const int j = tid / DD, d = tid % DD;
#pragma unroll
            for (int ch = 0; ch < 2; ++ch) {
                const float4 w0 = *reinterpret_cast<const float4*>(
                    W + (size_t)(j * CC + c0 + ch) * 128 + d * 8);
                const float4 w1 = *reinterpret_cast<const float4*>(
                    W + (size_t)(j * CC + c0 + ch) * 128 + d * 8 + 4);
                const float4 t0 = *reinterpret_cast<const float4*>(Tt + ch * 80 + j * 8);
                const float4 t1 = *reinterpret_cast<const float4*>(Tt + ch * 80 + j * 8 + 4);
                sreg = fmaf(w0.x, t0.x, sreg); sreg = fmaf(w0.y, t0.y, sreg);
                sreg = fmaf(w0.z, t0.z, sreg); sreg = fmaf(w0.w, t0.w, sreg);
                sreg = fmaf(w1.x, t1.x, sreg); sreg = fmaf(w1.y, t1.y, sreg);
                sreg = fmaf(w1.z, t1.z, sreg); sreg = fmaf(w1.w, t1.w, sreg);
            }
        }
    }

    // ---- publish partial, elect finisher ----
    if (tid < 160) g_part[((size_t)b * GC + gc) * 160 + tid] = sreg;
    __threadfence();
    __syncthreads();
    if (tid == 0) {
        const int old = atomicAdd(&g_cnt[b], 1);
        lastFlag = (old == GC - 1);
    }
    __syncthreads();

    if (lastFlag) {
        __threadfence();
        if (tid < 160) {
            float s = Bv[tid];
#pragma unroll
            for (int g2 = 0; g2 < GC; ++g2)
                s += g_part[((size_t)b * GC + g2) * 160 + tid];
            red[tid] = s;
        }
        __syncthreads();
        if (tid < JJ) {
            float sq = 0.f;
#pragma unroll
            for (int d = 0; d < DD; ++d) { const float v = red[tid * DD + d]; sq += v * v; }
            red[160 + tid] = sqrtf(sq) / (1.0f + sq);
        }
        __syncthreads();
        if (tid < 160) {
            const float o = red[tid] * red[160 + tid / DD];
            if (it == 0)      g_V[b * 160 + tid]  = o;
            else if (it == 1) g_V[b * 160 + tid] += o;
            else              out[(size_t)b * 160 + tid] = o;
        }
        if (tid == 0) g_cnt[b] = 0;   // clean for next launch / next replay
    }
}

// ---------------------------------------------------------------------------
extern "C" void kernel_launch(void* const* d_in, const int* in_sizes, int n_in,
                              void* d_out, int out_size) {
    const float* x  = (const float*)d_in[0];  // [128, 6400, 8]
    const float* W  = (const float*)d_in[1];  // [10, 32, 16, 8]
    const float* Bv = (const float*)d_in[2];  // [10, 16]
    float* out = (float*)d_out;               // [128, 10, 16]

    const dim3 gr(GC, BB);
    k_iter<<<gr, 256>>>(x, W, Bv, out, 0);
    k_iter<<<gr, 256>>>(x, W, Bv, out, 1);
    k_iter<<<gr, 256>>>(x, W, Bv, out, 2);
}

// round 5
// speedup vs baseline: 8.4720x; 1.0907x over previous
#include <cuda_runtime.h>
#include <math.h>

#define BB 128
#define JJ 10
#define DD 16
#define II 6400
#define KK 8
#define CC 32
#define REP 200        // capsules per channel
#define GC  16         // channel-groups per batch (2 channels each)

__device__ float g_Sx[BB * CC * KK];         // per-channel input sums
__device__ float g_V[BB * 160];              // V0 = outputs of iter 0
__device__ float g_part1[BB * GC * 160];     // iter-1 partial s
__device__ float g_part2[BB * GC * 160];     // iter-2 partial s

__device__ __forceinline__ void cp16(float* dst, const float* src) {
    unsigned sdst = (unsigned)__cvta_generic_to_shared(dst);
    asm volatile("cp.async.cg.shared.global [%0], [%1], 16;\n" :: "r"(sdst), "l"(src));
}
__device__ __forceinline__ void cp_commit() { asm volatile("cp.async.commit_group;\n"); }
__device__ __forceinline__ void cp_wait0()  { asm volatile("cp.async.wait_group 0;\n"); }

// ---------------------------------------------------------------------------
// k_sum: Sx[b,c,k] = sum_{i in channel c} x[b,i,k].  grid (CC, BB), block 128.
// Fully coalesced float4 reads; warp-shuffle reduce. DRAM-bound.
// ---------------------------------------------------------------------------
__global__ __launch_bounds__(128) void k_sum(const float* __restrict__ x) {
    const int c = blockIdx.x, b = blockIdx.y, tid = threadIdx.x;
    const float4* xp = reinterpret_cast<const float4*>(
        x + ((size_t)b * II + (size_t)c * REP) * KK);   // 400 float4

    float4 a = make_float4(0.f, 0.f, 0.f, 0.f);
    for (int p = tid; p < 400; p += 128) {              // p%2 == tid%2 (fixed k-half)
        const float4 v = xp[p];
        a.x += v.x; a.y += v.y; a.z += v.z; a.w += v.w;
    }
    // reduce across lanes of same parity
#pragma unroll
    for (int m = 2; m <= 16; m <<= 1) {
        a.x += __shfl_xor_sync(0xffffffffu, a.x, m);
        a.y += __shfl_xor_sync(0xffffffffu, a.y, m);
        a.z += __shfl_xor_sync(0xffffffffu, a.z, m);
        a.w += __shfl_xor_sync(0xffffffffu, a.w, m);
    }
    __shared__ float sred[4][2][4];
    const int w = tid >> 5, l = tid & 31;
    if (l < 2) { sred[w][l][0] = a.x; sred[w][l][1] = a.y;
                 sred[w][l][2] = a.z; sred[w][l][3] = a.w; }
    __syncthreads();
    if (tid < KK) {
        float s = 0.f;
#pragma unroll
        for (int ww = 0; ww < 4; ++ww) s += sred[ww][tid >> 2][tid & 3];
        g_Sx[(b * CC + c) * KK + tid] = s;
    }
}

// ---------------------------------------------------------------------------
// k_v0: V0[b,j,d] = squash_j(0.1 * sum_{c,k} W[j,c,d,k]*Sx[b,c,k] + B[j,d])
// grid BB, block 256 (160 active)
// ---------------------------------------------------------------------------
__global__ __launch_bounds__(256) void k_v0(const float* __restrict__ W,
                                            const float* __restrict__ Bv) {
    const int b = blockIdx.x, tid = threadIdx.x;
    __shared__ float Ss[CC * KK];
    __shared__ float sv[160];
    __shared__ float fb[JJ];
    if (tid < CC * KK) Ss[tid] = g_Sx[b * CC * KK + tid];
    __syncthreads();
    if (tid < 160) {
        const int j = tid / DD, d = tid % DD;
        float acc = 0.f;
#pragma unroll 4
        for (int c = 0; c < CC; ++c) {
            const float4 w0 = *reinterpret_cast<const float4*>(
                W + (size_t)(j * CC + c) * 128 + d * 8);
            const float4 w1 = *reinterpret_cast<const float4*>(
                W + (size_t)(j * CC + c) * 128 + d * 8 + 4);
            const float4 s0 = *reinterpret_cast<const float4*>(Ss + c * 8);
            const float4 s1 = *reinterpret_cast<const float4*>(Ss + c * 8 + 4);
            acc = fmaf(w0.x, s0.x, acc); acc = fmaf(w0.y, s0.y, acc);
            acc = fmaf(w0.z, s0.z, acc); acc = fmaf(w0.w, s0.w, acc);
            acc = fmaf(w1.x, s1.x, acc); acc = fmaf(w1.y, s1.y, acc);
            acc = fmaf(w1.z, s1.z, acc); acc = fmaf(w1.w, s1.w, acc);
        }
        sv[tid] = 0.1f * acc + Bv[tid];
    }
    __syncthreads();
    if (tid < JJ) {
        float sq = 0.f;
#pragma unroll
        for (int d = 0; d < DD; ++d) { const float v = sv[tid * DD + d]; sq += v * v; }
        fb[tid] = sqrtf(sq) / (1.0f + sq);
    }
    __syncthreads();
    if (tid < 160) g_V[b * 160 + tid] = sv[tid] * fb[tid / DD];
}

// ---------------------------------------------------------------------------
// k_route: one routing pass. grid (GC, BB), block 256. No atomics/fences.
//   it==1: V = g_V.   it==2: V = g_V + squash(sum_gc g_part1 + B)  (redundant recon)
//   writes per-block partial s into dst.
// ---------------------------------------------------------------------------
__global__ __launch_bounds__(256) void k_route(const float* __restrict__ x,
                                               const float* __restrict__ W,
                                               const float* __restrict__ Bv,
                                               int it) {
    __shared__ float xs[3200];     // [ch][i][k]
    __shared__ float Pq[160];      // [ch][j][k]
    __shared__ float cs[4400];     // [ch][i*11 + j]   (also aliased as recon scratch)
    __shared__ float part[960];
    __shared__ float Tt[160];
    __shared__ float Vs[160];

    const int gc  = blockIdx.x;
    const int b   = blockIdx.y;
    const int tid = threadIdx.x;
    const int c0  = gc * 2;
    const float* xb = x + ((size_t)b * II + (size_t)c0 * REP) * KK;

    for (int t = tid; t < 800; t += 256) cp16(xs + t * 4, xb + t * 4);
    cp_commit();

    if (it == 1) {
        if (tid < 160) Vs[tid] = g_V[b * 160 + tid];
    } else {
        float* red = cs;           // alias: cs unused until phase A
        if (tid < 160) {
            float s = Bv[tid];
#pragma unroll
            for (int g2 = 0; g2 < GC; ++g2)
                s += g_part1[((size_t)b * GC + g2) * 160 + tid];
            red[tid] = s;
        }
        __syncthreads();
        if (tid < JJ) {
            float sq = 0.f;
#pragma unroll
            for (int d = 0; d < DD; ++d) { const float v = red[tid * DD + d]; sq += v * v; }
            red[160 + tid] = sqrtf(sq) / (1.0f + sq);
        }
        __syncthreads();
        if (tid < 160) Vs[tid] = g_V[b * 160 + tid] + red[tid] * red[160 + tid / DD];
    }
    __syncthreads();

    // P[ch,j,k] = sum_d Vs[j,d] * W[j,c0+ch,d,k]
    if (tid < 160) {
        const int ch = tid / 80, r = tid % 80, j = r >> 3, k = r & 7;
        const float* Wp = W + ((size_t)(j * CC + c0 + ch)) * 128 + k;
        float acc = 0.f;
#pragma unroll
        for (int d = 0; d < DD; ++d) acc = fmaf(Vs[j * DD + d], Wp[d * 8], acc);
        Pq[ch * 80 + j * 8 + k] = acc;
    }
    cp_wait0();
    __syncthreads();

    // ---- phase A: logits + softmax -> coefs ----
    for (int cap = tid; cap < 2 * REP; cap += 256) {
        const int ch = (cap >= REP);
        const int i  = cap - ch * REP;
        const float4 xa = *reinterpret_cast<const float4*>(xs + ch * 1600 + i * 8);
        const float4 xc = *reinterpret_cast<const float4*>(xs + ch * 1600 + i * 8 + 4);
        float logit[JJ];
#pragma unroll
        for (int j = 0; j < JJ; ++j) {
            const float4 p0 = *reinterpret_cast<const float4*>(Pq + ch * 80 + j * 8);
            const float4 p1 = *reinterpret_cast<const float4*>(Pq + ch * 80 + j * 8 + 4);
            float l = 0.f;
            l = fmaf(xa.x, p0.x, l); l = fmaf(xa.y, p0.y, l);
            l = fmaf(xa.z, p0.z, l); l = fmaf(xa.w, p0.w, l);
            l = fmaf(xc.x, p1.x, l); l = fmaf(xc.y, p1.y, l);
            l = fmaf(xc.z, p1.z, l); l = fmaf(xc.w, p1.w, l);
            logit[j] = l;
        }
        float m = logit[0];
#pragma unroll
        for (int j = 1; j < JJ; ++j) m = fmaxf(m, logit[j]);
        float e[JJ], sum = 0.f;
#pragma unroll
        for (int j = 0; j < JJ; ++j) { e[j] = __expf(logit[j] - m); sum += e[j]; }
        const float r = __fdividef(1.0f, sum);
        float* cw = cs + ch * 2200 + i * 11;
#pragma unroll
        for (int j = 0; j < JJ; ++j) cw[j] = e[j] * r;
    }
    __syncthreads();

    // ---- phase B: partial T ----
    if (tid < 240) {
        const int chunk = tid / 40, g = tid % 40;
        const int ch = g / 20, r = g % 20, j = r >> 1, kh = r & 1;
        const int i0 = chunk * 34;
        const int i1 = (i0 + 34 < REP) ? i0 + 34 : REP;
        float a0 = 0.f, a1 = 0.f, a2 = 0.f, a3 = 0.f;
        const float* xp = xs + ch * 1600 + i0 * 8 + kh * 4;
        const float* cp = cs + ch * 2200 + i0 * 11 + j;
#pragma unroll 2
        for (int i = i0; i < i1; ++i) {
            const float4 xv = *reinterpret_cast<const float4*>(xp);
            const float cf = *cp;
            a0 = fmaf(cf, xv.x, a0); a1 = fmaf(cf, xv.y, a1);
            a2 = fmaf(cf, xv.z, a2); a3 = fmaf(cf, xv.w, a3);
            xp += 8; cp += 11;
        }
        *reinterpret_cast<float4*>(part + tid * 4) = make_float4(a0, a1, a2, a3);
    }
    __syncthreads();

    // ---- phase C: combine -> Tt ----
    if (tid < 160) {
        const int ch = tid / 80, r = tid % 80, j = r >> 3, k = r & 7;
        const int g = ch * 20 + j * 2 + (k >> 2), q = k & 3;
        float t = 0.f;
#pragma unroll
        for (int chunk = 0; chunk < 6; ++chunk)
            t += part[(chunk * 40 + g) * 4 + q];
        Tt[tid] = t;
    }
    __syncthreads();

    // ---- phase D: partial s -> global ----
    if (tid < 160) {
        const int j = tid / DD, d = tid % DD;
        float sreg = 0.f;
#pragma unroll
        for (int ch = 0; ch < 2; ++ch) {
            const float4 w0 = *reinterpret_cast<const float4*>(
                W + (size_t)(j * CC + c0 + ch) * 128 + d * 8);
            const float4 w1 = *reinterpret_cast<const float4*>(
                W + (size_t)(j * CC + c0 + ch) * 128 + d * 8 + 4);
            const float4 t0 = *reinterpret_cast<const float4*>(Tt + ch * 80 + j * 8);
            const float4 t1 = *reinterpret_cast<const float4*>(Tt + ch * 80 + j * 8 + 4);
            sreg = fmaf(w0.x, t0.x, sreg); sreg = fmaf(w0.y, t0.y, sreg);
            sreg = fmaf(w0.z, t0.z, sreg); sreg = fmaf(w0.w, t0.w, sreg);
            sreg = fmaf(w1.x, t1.x, sreg); sreg = fmaf(w1.y, t1.y, sreg);
            sreg = fmaf(w1.z, t1.z, sreg); sreg = fmaf(w1.w, t1.w, sreg);
        }
        float* dst = (it == 1) ? g_part1 : g_part2;
        dst[((size_t)b * GC + gc) * 160 + tid] = sreg;
    }
}

// ---------------------------------------------------------------------------
// k_final: out[b] = squash(sum_gc g_part2 + B).  grid BB, block 256.
// ---------------------------------------------------------------------------
__global__ __launch_bounds__(256) void k_final(const float* __restrict__ Bv,
                                               float* __restrict__ out) {
    const int b = blockIdx.x, tid = threadIdx.x;
    __shared__ float sv[160];
    __shared__ float fb[JJ];
    if (tid < 160) {
        float s = Bv[tid];
#pragma unroll
        for (int g2 = 0; g2 < GC; ++g2)
            s += g_part2[((size_t)b * GC + g2) * 160 + tid];
        sv[tid] = s;
    }
    __syncthreads();
    if (tid < JJ) {
        float sq = 0.f;
#pragma unroll
        for (int d = 0; d < DD; ++d) { const float v = sv[tid * DD + d]; sq += v * v; }
        fb[tid] = sqrtf(sq) / (1.0f + sq);
    }
    __syncthreads();
    if (tid < 160) out[(size_t)b * 160 + tid] = sv[tid] * fb[tid / DD];
}

// ---------------------------------------------------------------------------
extern "C" void kernel_launch(void* const* d_in, const int* in_sizes, int n_in,
                              void* d_out, int out_size) {
    const float* x  = (const float*)d_in[0];  // [128, 6400, 8]
    const float* W  = (const float*)d_in[1];  // [10, 32, 16, 8]
    const float* Bv = (const float*)d_in[2];  // [10, 16]
    float* out = (float*)d_out;               // [128, 10, 16]

    k_sum<<<dim3(CC, BB), 128>>>(x);
    k_v0<<<BB, 256>>>(W, Bv);
    k_route<<<dim3(GC, BB), 256>>>(x, W, Bv, 1);
    k_route<<<dim3(GC, BB), 256>>>(x, W, Bv, 2);
    k_final<<<BB, 256>>>(Bv, out);
}